// round 14
// baseline (speedup 1.0000x reference)
#include <cuda_runtime.h>
#include <cuda_fp16.h>
#include <math.h>
#include <float.h>
#include <stdint.h>

#define Bsz   4096
#define Dh    1024
#define Cdim  128
#define KSEL  10
#define RTOT  8192
#define CBLK  64
#define NTILE 2080          // 64*65/2 lower-triangular tiles

// ---------------- scratch ----------------
__device__ float     g_v[Bsz];
__device__ float     g_sq[Bsz];                // cc * vc^2
__device__ uint32_t  g_mask[Bsz][4];
__device__ uint32_t  g_adj[Bsz * (Bsz / 32)];
__device__ float2    g_part[(size_t)RTOT * CBLK];
__device__ float     g_pos[Bsz];
__device__ float     g_row[RTOT];
__device__ __align__(256) __half g_hf[(size_t)RTOT * Dh];   // 16MB fp16 plane

// ================= helpers =================
__device__ __forceinline__ uint32_t smem_u32(const void* p) {
    uint32_t a;
    asm("{ .reg .u64 t; cvta.to.shared.u64 t, %1; cvt.u32.u64 %0, t; }" : "=r"(a) : "l"(p));
    return a;
}
__device__ __forceinline__ void cp16(uint32_t d, const void* s) {
    asm volatile("cp.async.ca.shared.global [%0], [%1], 16;" :: "r"(d), "l"(s) : "memory");
}
#define CP_COMMIT() asm volatile("cp.async.commit_group;" ::: "memory")
#define CP_WAIT0()  asm volatile("cp.async.wait_group 0;" ::: "memory")
#define LDSM4(r0, r1, r2, r3, a) \
    asm volatile("ldmatrix.sync.aligned.m8n8.x4.shared.b16 {%0,%1,%2,%3}, [%4];" \
        : "=r"(r0), "=r"(r1), "=r"(r2), "=r"(r3) : "r"(a))

__device__ __forceinline__ void mma_fp16(float* d, const uint32_t* a, const uint32_t* b) {
    asm volatile(
        "mma.sync.aligned.m16n8k16.row.col.f32.f16.f16.f32 "
        "{%0,%1,%2,%3}, {%4,%5,%6,%7}, {%8,%9}, {%0,%1,%2,%3};"
        : "+f"(d[0]), "+f"(d[1]), "+f"(d[2]), "+f"(d[3])
        : "r"(a[0]), "r"(a[1]), "r"(a[2]), "r"(a[3]), "r"(b[0]), "r"(b[1]));
}
__device__ __forceinline__ void lse_merge(float& M, float& S, float m2, float s2) {
    if (m2 > M) { S = s2 + S * __expf(M - m2); M = m2; }
    else if (s2 > 0.0f) { S += s2 * __expf(m2 - M); }
}

// ---------------- Kernel A: mask P by row max (+ per-row cc*v^2) ----------------
__global__ void maskP_kernel(const float* __restrict__ P) {
    int warp = (blockIdx.x * blockDim.x + threadIdx.x) >> 5;
    int lane = threadIdx.x & 31;
    if (warp >= Bsz) return;
    const float* row = P + (size_t)warp * Cdim;
    float v[4];
    float m = -FLT_MAX;
#pragma unroll
    for (int j = 0; j < 4; j++) { v[j] = row[j * 32 + lane]; m = fmaxf(m, v[j]); }
#pragma unroll
    for (int o = 16; o; o >>= 1) m = fmaxf(m, __shfl_xor_sync(0xffffffffu, m, o));
    int cnt = 0;
#pragma unroll
    for (int j = 0; j < 4; j++) {
        uint32_t b = __ballot_sync(0xffffffffu, v[j] == m);
        cnt += __popc(b);
        if (lane == 0) g_mask[warp][j] = b;
    }
    if (lane == 0) { g_v[warp] = m; g_sq[warp] = (float)cnt * m * m; }
}

// ---------------- Kernel B: adjacency, 4 rows per block (column data reused 4x) ----------------
__global__ __launch_bounds__(256) void adj_kernel(const float* __restrict__ noise) {
    __shared__ float wval[4][128];
    __shared__ int   widx[4][128];
    __shared__ int   winlist[4][16];
    int r0 = blockIdx.x * 4;
    int t = threadIdx.x;      // 256
    int lane = t & 31, w = t >> 5;

    uint32_t rm[4][4];
    float vr4[4], sqr4[4];
#pragma unroll
    for (int p = 0; p < 4; p++) {
#pragma unroll
        for (int j = 0; j < 4; j++) rm[p][j] = g_mask[r0 + p][j];
        vr4[p] = g_v[r0 + p];
        sqr4[p] = g_sq[r0 + p];
    }

    // phase 1: thread-local top-8 smallest d^2 over 16 columns, for 4 rows
    float tv[4][8]; int ti[4][8];
#pragma unroll
    for (int p = 0; p < 4; p++)
#pragma unroll
        for (int i = 0; i < 8; i++) { tv[p][i] = FLT_MAX; ti[p][i] = -1; }
#pragma unroll 4
    for (int i = 0; i < 16; i++) {
        int c = i * 256 + t;
        uint32_t cm0 = g_mask[c][0], cm1 = g_mask[c][1], cm2 = g_mask[c][2], cm3 = g_mask[c][3];
        float vc = g_v[c], sqc = g_sq[c];
#pragma unroll
        for (int p = 0; p < 4; p++) {
            int nc = __popc(rm[p][0] & cm0) + __popc(rm[p][1] & cm1) +
                     __popc(rm[p][2] & cm2) + __popc(rm[p][3] & cm3);
            float d2 = sqr4[p] + sqc - 2.0f * vr4[p] * vc * (float)nc;
            if (d2 < tv[p][7]) {
                tv[p][7] = d2; ti[p][7] = c;
#pragma unroll
                for (int j = 7; j > 0; j--) {
                    if (tv[p][j] < tv[p][j - 1]) {
                        float tf = tv[p][j - 1]; tv[p][j - 1] = tv[p][j]; tv[p][j] = tf;
                        int tx = ti[p][j - 1]; ti[p][j - 1] = ti[p][j]; ti[p][j] = tx;
                    } else break;
                }
            }
        }
    }

    // phase 2: per-warp top-16 per row (argmin with list advance)
#pragma unroll
    for (int p = 0; p < 4; p++) {
#pragma unroll
        for (int it = 0; it < 16; it++) {
            float bv = tv[p][0]; int bl = lane;
#pragma unroll
            for (int o = 16; o; o >>= 1) {
                float ov = __shfl_xor_sync(0xffffffffu, bv, o);
                int   ol = __shfl_xor_sync(0xffffffffu, bl, o);
                if (ov < bv || (ov == bv && ol < bl)) { bv = ov; bl = ol; }
            }
            int bidx = __shfl_sync(0xffffffffu, ti[p][0], bl);
            if (lane == 0) { wval[p][w * 16 + it] = bv; widx[p][w * 16 + it] = bidx; }
            if (lane == bl) {
#pragma unroll
                for (int j = 0; j < 7; j++) { tv[p][j] = tv[p][j + 1]; ti[p][j] = ti[p][j + 1]; }
                tv[p][7] = FLT_MAX;
            }
        }
    }
    __syncthreads();

    // phase 3: warps 0-3 (one per row) — top-20 of 128 by d^2, exact S, top-10 by S
    if (w < 4) {
        int p = w;
        int r = r0 + p;
        float cvv[4]; int cii[4];
#pragma unroll
        for (int j = 0; j < 4; j++) { cvv[j] = wval[p][j * 32 + lane]; cii[j] = widx[p][j * 32 + lane]; }
        float myd2 = FLT_MAX; int myidx = -1;
#pragma unroll
        for (int it = 0; it < 20; it++) {
            float bv = cvv[0]; int bi = cii[0];
            if (cvv[1] < bv) { bv = cvv[1]; bi = cii[1]; }
            if (cvv[2] < bv) { bv = cvv[2]; bi = cii[2]; }
            if (cvv[3] < bv) { bv = cvv[3]; bi = cii[3]; }
            int bl = lane;
            float rv = bv; int rl = bl;
#pragma unroll
            for (int o = 16; o; o >>= 1) {
                float ov = __shfl_xor_sync(0xffffffffu, rv, o);
                int   ol = __shfl_xor_sync(0xffffffffu, rl, o);
                if (ov < rv || (ov == rv && ol < rl)) { rv = ov; rl = ol; }
            }
            int bidx = __shfl_sync(0xffffffffu, bi, rl);
            if (lane == it) { myd2 = rv; myidx = bidx; }
            if (lane == rl) {
                if      (cvv[0] == rv && cii[0] == bidx) cvv[0] = FLT_MAX;
                else if (cvv[1] == rv && cii[1] == bidx) cvv[1] = FLT_MAX;
                else if (cvv[2] == rv && cii[2] == bidx) cvv[2] = FLT_MAX;
                else                                     cvv[3] = FLT_MAX;
            }
        }
        float s;
        if (lane < 20 && myidx >= 0) {
            float d2c = fmaxf(myd2, 0.0f);
            float nz = noise[(size_t)r * Bsz + myidx];
            s = -(sqrtf(d2c) + 1e-4f * nz - (myidx == r ? 1.0f : 0.0f));
        } else s = -FLT_MAX;
#pragma unroll
        for (int it = 0; it < 10; it++) {
            float rv = s; int rl = lane;
#pragma unroll
            for (int o = 16; o; o >>= 1) {
                float ov = __shfl_xor_sync(0xffffffffu, rv, o);
                int   ol = __shfl_xor_sync(0xffffffffu, rl, o);
                if (ov > rv || (ov == rv && ol < rl)) { rv = ov; rl = ol; }
            }
            int bidx = __shfl_sync(0xffffffffu, myidx, rl);
            if (lane == 0) winlist[p][it] = bidx;
            if (lane == rl) s = -FLT_MAX;
        }
    }
    __syncthreads();

    // phase 4: emit bitmask rows (10 set bits each)
    if (t < 128) {
#pragma unroll
        for (int p = 0; p < 4; p++) {
            uint32_t word = 0;
#pragma unroll
            for (int j = 0; j < 10; j++) {
                int ix = winlist[p][j];
                if ((ix >> 5) == t) word |= 1u << (ix & 31);
            }
            g_adj[(r0 + p) * 128 + t] = word;
        }
    }
}

// ---------------- fused: fp16 convert + pos logits (one warp per row pair) ----------------
__global__ void splitpos_kernel(const float* __restrict__ hi, const float* __restrict__ hj) {
    int warp = (blockIdx.x * blockDim.x + threadIdx.x) >> 5;   // 0..4095
    int lane = threadIdx.x & 31;
    if (warp >= Bsz) return;
    const float4* a = (const float4*)(hi + (size_t)warp * Dh);
    const float4* b = (const float4*)(hj + (size_t)warp * Dh);
    __half2* da = (__half2*)(g_hf + (size_t)warp * Dh);
    __half2* db = (__half2*)(g_hf + (size_t)(warp + Bsz) * Dh);
    float s = 0.0f;
    for (int i = lane; i < Dh / 4; i += 32) {
        float4 x = a[i], y = b[i];
        s += x.x * y.x + x.y * y.y + x.z * y.z + x.w * y.w;
        da[i * 2]     = __floats2half2_rn(x.x, x.y);
        da[i * 2 + 1] = __floats2half2_rn(x.z, x.w);
        db[i * 2]     = __floats2half2_rn(y.x, y.y);
        db[i * 2 + 1] = __floats2half2_rn(y.z, y.w);
    }
#pragma unroll
    for (int o = 16; o; o >>= 1) s += __shfl_xor_sync(0xffffffffu, s, o);
    if (lane == 0) g_pos[warp] = s * 2.0f;   // /temperature(0.5)
}

// ---------------- sim GEMM: fp16, KC=64 chunks, triangular tiles (R12-proven) ----------------
#define ROWB 144                      // 128B data + 16B pad (conflict-free ldmatrix)
#define PLANE_B (128 * ROWB)          // 18432
#define STAGE_B (2 * PLANE_B)         // 36864: A, B
#define SMEM_MMA (2 * STAGE_B)        // 73728 (tile 128*129*4=66048 fits in reuse)
#define NC (Dh / 64)                  // 16 k-chunks of 64
#define TSTRIDE 129                   // tile row stride in floats

__global__ __launch_bounds__(256, 2)
void sim_mma_kernel() {
    extern __shared__ __align__(128) char smem[];
    uint32_t sb = smem_u32(smem);
    int tid = threadIdx.x;
    int lane = tid & 31;
    int wid = tid >> 5;
    int warp_m = wid >> 2;
    int warp_n = wid & 3;

    // decode lower-triangular tile (bi >= bj)
    int tix = blockIdx.x;
    int bi = (int)((sqrtf(8.0f * (float)tix + 1.0f) - 1.0f) * 0.5f);
    while ((bi + 1) * (bi + 2) / 2 <= tix) bi++;
    while (bi * (bi + 1) / 2 > tix) bi--;
    int bj = tix - bi * (bi + 1) / 2;
    int rbase = bi * 128;
    int cbase = bj * 128;

    float acc[4][4][4];
#pragma unroll
    for (int mt = 0; mt < 4; mt++)
#pragma unroll
        for (int nt = 0; nt < 4; nt++)
#pragma unroll
            for (int q = 0; q < 4; q++) acc[mt][nt][q] = 0.0f;

    // 2048 x 16B lines per chunk, 8 per thread
    auto issue = [&](int kc, int buf) {
#pragma unroll
        for (int i = 0; i < 8; i++) {
            int plane = i >> 2;                    // 0:A 1:B
            int idx = tid + (i & 3) * 256;         // 0..1023
            int row = idx >> 3;                    // 0..127
            int q = idx & 7;                       // 16B chunk in 128B row
            int grow = ((plane == 0) ? rbase : cbase) + row;
            const __half* src = g_hf + (size_t)grow * Dh + kc * 64 + q * 8;
            uint32_t dst = sb + buf * STAGE_B + plane * PLANE_B + row * ROWB + q * 16;
            cp16(dst, src);
        }
        CP_COMMIT();
    };

    uint32_t a_off = (uint32_t)((warp_m * 64 + (lane & 15)) * ROWB + ((lane >> 4) & 1) * 16);
    int bmat = lane >> 3, brin = lane & 7;
    uint32_t b_row0 = (uint32_t)(warp_n * 32 + ((bmat >> 1) & 1) * 8 + brin);
    uint32_t b_off = b_row0 * ROWB + (uint32_t)((bmat & 1) * 16);

    issue(0, 0);
    for (int kc = 0; kc < NC; kc++) {
        int buf = kc & 1;
        CP_WAIT0();              // chunk for buf (issued last iter) has landed
        __syncthreads();         // and everyone finished reading buf^1
        if (kc + 1 < NC) issue(kc + 1, buf ^ 1);

        uint32_t st = sb + buf * STAGE_B;
#pragma unroll
        for (int ks = 0; ks < 4; ks++) {
            uint32_t ah[4][4], bh[4][2];
#pragma unroll
            for (int mt = 0; mt < 4; mt++) {
                uint32_t addr = st + a_off + (uint32_t)(mt * 16 * ROWB + ks * 32);
                LDSM4(ah[mt][0], ah[mt][1], ah[mt][2], ah[mt][3], addr);
            }
#pragma unroll
            for (int p = 0; p < 2; p++) {
                uint32_t addr = st + PLANE_B + b_off + (uint32_t)(p * 16 * ROWB + ks * 32);
                uint32_t r0, r1, r2, r3;
                LDSM4(r0, r1, r2, r3, addr);
                bh[p * 2][0] = r0; bh[p * 2][1] = r1; bh[p * 2 + 1][0] = r2; bh[p * 2 + 1][1] = r3;
            }
#pragma unroll
            for (int mt = 0; mt < 4; mt++)
#pragma unroll
                for (int nt = 0; nt < 4; nt++) mma_fp16(acc[mt][nt], ah[mt], bh[nt]);
        }
    }
    __syncthreads();   // last compute done before smem reuse as tile

    // ---- stage scaled tile (x2 = /temperature) into smem [128][129] ----
    float* tile = (float*)smem;
#pragma unroll
    for (int mt = 0; mt < 4; mt++) {
#pragma unroll
        for (int h = 0; h < 2; h++) {
            int rloc = warp_m * 64 + mt * 16 + h * 8 + (lane >> 2);
#pragma unroll
            for (int nt = 0; nt < 4; nt++) {
                int c = warp_n * 32 + nt * 8 + (lane & 3) * 2;
                tile[rloc * TSTRIDE + c]     = acc[mt][nt][h * 2 + 0] * 2.0f;
                tile[rloc * TSTRIDE + c + 1] = acc[mt][nt][h * 2 + 1] * 2.0f;
            }
        }
    }
    __syncthreads();

    // ---- dual-sided masked LSE over the tile ----
    if (tid < 128) {
        int rmod = (rbase + tid) & (Bsz - 1);
        int cw0 = ((cbase & (Bsz - 1)) >> 5);
        uint32_t w[4];
#pragma unroll
        for (int q = 0; q < 4; q++) w[q] = g_adj[rmod * (Bsz / 32) + cw0 + q];
        const float* rowp = tile + tid * TSTRIDE;
        float M = -FLT_MAX;
#pragma unroll 4
        for (int c = 0; c < 128; c++) {
            if (!((w[c >> 5] >> (c & 31)) & 1u)) M = fmaxf(M, rowp[c]);
        }
        float S = 0.0f;
        if (M > -FLT_MAX * 0.5f) {
#pragma unroll 4
            for (int c = 0; c < 128; c++) {
                if (!((w[c >> 5] >> (c & 31)) & 1u)) S += __expf(rowp[c] - M);
            }
        }
        g_part[(size_t)(rbase + tid) * CBLK + bj] = make_float2(M, S);
    } else if (bi != bj) {
        int u = tid - 128;
        int rmod = (cbase + u) & (Bsz - 1);
        int cw0 = ((rbase & (Bsz - 1)) >> 5);
        uint32_t w[4];
#pragma unroll
        for (int q = 0; q < 4; q++) w[q] = g_adj[rmod * (Bsz / 32) + cw0 + q];
        const float* colp = tile + u;
        float M = -FLT_MAX;
#pragma unroll 4
        for (int r = 0; r < 128; r++) {
            if (!((w[r >> 5] >> (r & 31)) & 1u)) M = fmaxf(M, colp[r * TSTRIDE]);
        }
        float S = 0.0f;
        if (M > -FLT_MAX * 0.5f) {
#pragma unroll 4
            for (int r = 0; r < 128; r++) {
                if (!((w[r >> 5] >> (r & 31)) & 1u)) S += __expf(colp[r * TSTRIDE] - M);
            }
        }
        g_part[(size_t)(cbase + u) * CBLK + bi] = make_float2(M, S);
    }
}

// ---------------- finalize stage 1: one warp per row ----------------
__global__ void rowlse_kernel() {
    int warp = (blockIdx.x * blockDim.x + threadIdx.x) >> 5;   // 0..8191
    int lane = threadIdx.x & 31;
    const float2* p = &g_part[(size_t)warp * CBLK];
    float M = -FLT_MAX, S = 0.0f;
    float2 q0 = p[lane];
    float2 q1 = p[lane + 32];
    lse_merge(M, S, q0.x, q0.y);
    lse_merge(M, S, q1.x, q1.y);
#pragma unroll
    for (int o = 16; o; o >>= 1) {
        float m2 = __shfl_xor_sync(0xffffffffu, M, o);
        float s2 = __shfl_xor_sync(0xffffffffu, S, o);
        lse_merge(M, S, m2, s2);
    }
    if (lane == 0) {
        float pos = g_pos[warp & (Bsz - 1)];
        lse_merge(M, S, pos, 1.0f);
        g_row[warp] = (M + __logf(S)) - pos;
    }
}

// ---------------- finalize stage 2 ----------------
__global__ void final_reduce(float* __restrict__ out) {
    __shared__ double sred[256];
    int t = threadIdx.x;
    double acc = 0.0;
    for (int r = t; r < RTOT; r += 256) acc += (double)g_row[r];
    sred[t] = acc;
    __syncthreads();
    for (int o = 128; o; o >>= 1) {
        if (t < o) sred[t] += sred[t + o];
        __syncthreads();
    }
    if (t == 0) out[0] = (float)(sred[0] / (double)RTOT);
}

// ---------------- launch ----------------
extern "C" void kernel_launch(void* const* d_in, const int* in_sizes, int n_in,
                              void* d_out, int out_size) {
    const float* hi    = (const float*)d_in[0];
    const float* hj    = (const float*)d_in[1];
    const float* P     = (const float*)d_in[2];
    const float* noise = (const float*)d_in[3];
    (void)in_sizes; (void)n_in; (void)out_size;

    static int smem_set = 0;
    if (!smem_set) {
        cudaFuncSetAttribute(sim_mma_kernel, cudaFuncAttributeMaxDynamicSharedMemorySize, SMEM_MMA);
        smem_set = 1;
    }

    maskP_kernel<<<(Bsz * 32 + 255) / 256, 256>>>(P);
    adj_kernel<<<Bsz / 4, 256>>>(noise);
    splitpos_kernel<<<Bsz * 32 / 256, 256>>>(hi, hj);
    sim_mma_kernel<<<NTILE, 256, SMEM_MMA>>>();
    rowlse_kernel<<<RTOT * 32 / 256, 256>>>();
    final_reduce<<<1, 256>>>((float*)d_out);
}

// round 15
// speedup vs baseline: 1.0686x; 1.0686x over previous
#include <cuda_runtime.h>
#include <cuda_fp16.h>
#include <math.h>
#include <float.h>
#include <stdint.h>

#define Bsz   4096
#define Dh    1024
#define Cdim  128
#define KSEL  10
#define RTOT  8192
#define CBLK  64
#define NTILE 2080          // 64*65/2 lower-triangular tiles

// ---------------- scratch ----------------
__device__ float     g_v[Bsz];
__device__ float     g_sq[Bsz];                // cc * vc^2
__device__ float2    g_vsq[Bsz];               // (v, cc*v^2) packed
__device__ signed char g_amax[Bsz];            // argmax if unique, else -1
__device__ uint32_t  g_mask[Bsz][4];
__device__ uint32_t  g_adj[Bsz * (Bsz / 32)];
__device__ float2    g_part[(size_t)RTOT * CBLK];
__device__ float     g_pos[Bsz];
__device__ float     g_row[RTOT];
__device__ __align__(256) __half g_hf[(size_t)RTOT * Dh];   // 16MB fp16 plane

// ================= helpers =================
__device__ __forceinline__ uint32_t smem_u32(const void* p) {
    uint32_t a;
    asm("{ .reg .u64 t; cvta.to.shared.u64 t, %1; cvt.u32.u64 %0, t; }" : "=r"(a) : "l"(p));
    return a;
}
__device__ __forceinline__ void cp16(uint32_t d, const void* s) {
    asm volatile("cp.async.ca.shared.global [%0], [%1], 16;" :: "r"(d), "l"(s) : "memory");
}
#define CP_COMMIT() asm volatile("cp.async.commit_group;" ::: "memory")
#define CP_WAIT0()  asm volatile("cp.async.wait_group 0;" ::: "memory")
#define LDSM4(r0, r1, r2, r3, a) \
    asm volatile("ldmatrix.sync.aligned.m8n8.x4.shared.b16 {%0,%1,%2,%3}, [%4];" \
        : "=r"(r0), "=r"(r1), "=r"(r2), "=r"(r3) : "r"(a))

__device__ __forceinline__ void mma_fp16(float* d, const uint32_t* a, const uint32_t* b) {
    asm volatile(
        "mma.sync.aligned.m16n8k16.row.col.f32.f16.f16.f32 "
        "{%0,%1,%2,%3}, {%4,%5,%6,%7}, {%8,%9}, {%0,%1,%2,%3};"
        : "+f"(d[0]), "+f"(d[1]), "+f"(d[2]), "+f"(d[3])
        : "r"(a[0]), "r"(a[1]), "r"(a[2]), "r"(a[3]), "r"(b[0]), "r"(b[1]));
}
__device__ __forceinline__ void lse_merge(float& M, float& S, float m2, float s2) {
    if (m2 > M) { S = s2 + S * __expf(M - m2); M = m2; }
    else if (s2 > 0.0f) { S += s2 * __expf(m2 - M); }
}

// ---------------- Kernel A: mask P by row max (+ amax / packed v,sq) ----------------
__global__ void maskP_kernel(const float* __restrict__ P) {
    int warp = (blockIdx.x * blockDim.x + threadIdx.x) >> 5;
    int lane = threadIdx.x & 31;
    if (warp >= Bsz) return;
    const float* row = P + (size_t)warp * Cdim;
    float v[4];
    float m = -FLT_MAX;
#pragma unroll
    for (int j = 0; j < 4; j++) { v[j] = row[j * 32 + lane]; m = fmaxf(m, v[j]); }
#pragma unroll
    for (int o = 16; o; o >>= 1) m = fmaxf(m, __shfl_xor_sync(0xffffffffu, m, o));
    uint32_t bb[4];
    int cnt = 0;
#pragma unroll
    for (int j = 0; j < 4; j++) {
        bb[j] = __ballot_sync(0xffffffffu, v[j] == m);
        cnt += __popc(bb[j]);
        if (lane == 0) g_mask[warp][j] = bb[j];
    }
    if (lane == 0) {
        int amax = -1;
#pragma unroll
        for (int j = 3; j >= 0; j--) {
            if (bb[j]) amax = j * 32 + __ffs(bb[j]) - 1;   // lowest set bit overall
        }
        g_v[warp] = m;
        g_sq[warp] = (float)cnt * m * m;
        g_vsq[warp] = make_float2(m, (float)cnt * m * m);
        g_amax[warp] = (cnt == 1) ? (signed char)amax : (signed char)(-1);
    }
}

// ---------------- Kernel B: adjacency via d^2 top-k (argmax fast path) ----------------
__global__ __launch_bounds__(256) void adj_kernel(const float* __restrict__ noise) {
    __shared__ float wval[128];
    __shared__ int   widx[128];
    __shared__ int   winlist[16];
    int r = blockIdx.x;
    int t = threadIdx.x;      // 256
    int lane = t & 31, w = t >> 5;

    float vr = g_v[r];
    float sqr = g_sq[r];
    int ar = g_amax[r];

    // phase 1: thread-local top-8 smallest d^2 over 16 columns
    float tv[8]; int ti[8];
#pragma unroll
    for (int i = 0; i < 8; i++) { tv[i] = FLT_MAX; ti[i] = -1; }

    if (ar >= 0) {
        // fast path: row max is unique -> ncommon is a byte compare (exact)
        float two_vr = 2.0f * vr;
#pragma unroll
        for (int i = 0; i < 16; i++) {
            int c = i * 256 + t;
            int ac = g_amax[c];
            float2 vs = g_vsq[c];
            float d2;
            if (ac >= 0) {
                d2 = sqr + vs.y - ((ac == ar) ? two_vr * vs.x : 0.0f);
            } else {
                // column has tied maxima: exact bit test (cnt_r==1)
                int nc = (g_mask[c][ar >> 5] >> (ar & 31)) & 1;
                d2 = sqr + vs.y - two_vr * vs.x * (float)nc;
            }
            if (d2 < tv[7]) {
                tv[7] = d2; ti[7] = c;
#pragma unroll
                for (int j = 7; j > 0; j--) {
                    if (tv[j] < tv[j - 1]) {
                        float tf = tv[j - 1]; tv[j - 1] = tv[j]; tv[j] = tf;
                        int tx = ti[j - 1]; ti[j - 1] = ti[j]; ti[j] = tx;
                    } else break;
                }
            }
        }
    } else {
        // general path: full popcount (exact, rare)
        uint32_t mr0 = g_mask[r][0], mr1 = g_mask[r][1], mr2 = g_mask[r][2], mr3 = g_mask[r][3];
#pragma unroll
        for (int i = 0; i < 16; i++) {
            int c = i * 256 + t;
            int nc = __popc(mr0 & g_mask[c][0]) + __popc(mr1 & g_mask[c][1]) +
                     __popc(mr2 & g_mask[c][2]) + __popc(mr3 & g_mask[c][3]);
            float2 vs = g_vsq[c];
            float d2 = sqr + vs.y - 2.0f * vr * vs.x * (float)nc;
            if (d2 < tv[7]) {
                tv[7] = d2; ti[7] = c;
#pragma unroll
                for (int j = 7; j > 0; j--) {
                    if (tv[j] < tv[j - 1]) {
                        float tf = tv[j - 1]; tv[j - 1] = tv[j]; tv[j] = tf;
                        int tx = ti[j - 1]; ti[j - 1] = ti[j]; ti[j] = tx;
                    } else break;
                }
            }
        }
    }

    // phase 2: per-warp top-16 (argmin with list advance)
#pragma unroll
    for (int it = 0; it < 16; it++) {
        float bv = tv[0]; int bl = lane;
#pragma unroll
        for (int o = 16; o; o >>= 1) {
            float ov = __shfl_xor_sync(0xffffffffu, bv, o);
            int   ol = __shfl_xor_sync(0xffffffffu, bl, o);
            if (ov < bv || (ov == bv && ol < bl)) { bv = ov; bl = ol; }
        }
        int bidx = __shfl_sync(0xffffffffu, ti[0], bl);
        if (lane == 0) { wval[w * 16 + it] = bv; widx[w * 16 + it] = bidx; }
        if (lane == bl) {
#pragma unroll
            for (int j = 0; j < 7; j++) { tv[j] = tv[j + 1]; ti[j] = ti[j + 1]; }
            tv[7] = FLT_MAX;
        }
    }
    __syncthreads();

    // phase 3 (warp 0): top-20 of 128 by d^2, exact S on those, top-10 by S
    if (w == 0) {
        float cvv[4]; int cii[4];
#pragma unroll
        for (int j = 0; j < 4; j++) { cvv[j] = wval[j * 32 + lane]; cii[j] = widx[j * 32 + lane]; }
        float myd2 = FLT_MAX; int myidx = -1;
#pragma unroll
        for (int it = 0; it < 20; it++) {
            float bv = cvv[0]; int bi = cii[0];
            if (cvv[1] < bv) { bv = cvv[1]; bi = cii[1]; }
            if (cvv[2] < bv) { bv = cvv[2]; bi = cii[2]; }
            if (cvv[3] < bv) { bv = cvv[3]; bi = cii[3]; }
            int bl = lane;
            float rv = bv; int rl = bl;
#pragma unroll
            for (int o = 16; o; o >>= 1) {
                float ov = __shfl_xor_sync(0xffffffffu, rv, o);
                int   ol = __shfl_xor_sync(0xffffffffu, rl, o);
                if (ov < rv || (ov == rv && ol < rl)) { rv = ov; rl = ol; }
            }
            int bidx = __shfl_sync(0xffffffffu, bi, rl);
            if (lane == it) { myd2 = rv; myidx = bidx; }
            if (lane == rl) {
                if      (cvv[0] == rv && cii[0] == bidx) cvv[0] = FLT_MAX;
                else if (cvv[1] == rv && cii[1] == bidx) cvv[1] = FLT_MAX;
                else if (cvv[2] == rv && cii[2] == bidx) cvv[2] = FLT_MAX;
                else                                     cvv[3] = FLT_MAX;
            }
        }
        float s;
        if (lane < 20 && myidx >= 0) {
            float d2c = fmaxf(myd2, 0.0f);
            float nz = noise[(size_t)r * Bsz + myidx];
            s = -(sqrtf(d2c) + 1e-4f * nz - (myidx == r ? 1.0f : 0.0f));
        } else s = -FLT_MAX;
#pragma unroll
        for (int it = 0; it < 10; it++) {
            float rv = s; int rl = lane;
#pragma unroll
            for (int o = 16; o; o >>= 1) {
                float ov = __shfl_xor_sync(0xffffffffu, rv, o);
                int   ol = __shfl_xor_sync(0xffffffffu, rl, o);
                if (ov > rv || (ov == rv && ol < rl)) { rv = ov; rl = ol; }
            }
            int bidx = __shfl_sync(0xffffffffu, myidx, rl);
            if (lane == 0) winlist[it] = bidx;
            if (lane == rl) s = -FLT_MAX;
        }
    }
    __syncthreads();

    // phase 4: emit bitmask row (10 set bits)
    if (t < 128) {
        uint32_t word = 0;
#pragma unroll
        for (int j = 0; j < 10; j++) {
            int ix = winlist[j];
            if ((ix >> 5) == t) word |= 1u << (ix & 31);
        }
        g_adj[r * 128 + t] = word;
    }
}

// ---------------- fused: fp16 convert + pos logits (one warp per row pair) ----------------
__global__ void splitpos_kernel(const float* __restrict__ hi, const float* __restrict__ hj) {
    int warp = (blockIdx.x * blockDim.x + threadIdx.x) >> 5;   // 0..4095
    int lane = threadIdx.x & 31;
    if (warp >= Bsz) return;
    const float4* a = (const float4*)(hi + (size_t)warp * Dh);
    const float4* b = (const float4*)(hj + (size_t)warp * Dh);
    __half2* da = (__half2*)(g_hf + (size_t)warp * Dh);
    __half2* db = (__half2*)(g_hf + (size_t)(warp + Bsz) * Dh);
    float s = 0.0f;
    for (int i = lane; i < Dh / 4; i += 32) {
        float4 x = a[i], y = b[i];
        s += x.x * y.x + x.y * y.y + x.z * y.z + x.w * y.w;
        da[i * 2]     = __floats2half2_rn(x.x, x.y);
        da[i * 2 + 1] = __floats2half2_rn(x.z, x.w);
        db[i * 2]     = __floats2half2_rn(y.x, y.y);
        db[i * 2 + 1] = __floats2half2_rn(y.z, y.w);
    }
#pragma unroll
    for (int o = 16; o; o >>= 1) s += __shfl_xor_sync(0xffffffffu, s, o);
    if (lane == 0) g_pos[warp] = s * 2.0f;   // /temperature(0.5)
}

// ---------------- sim GEMM: fp16, KC=64 chunks, triangular tiles (R12-proven) ----------------
#define ROWB 144                      // 128B data + 16B pad (conflict-free ldmatrix)
#define PLANE_B (128 * ROWB)          // 18432
#define STAGE_B (2 * PLANE_B)         // 36864: A, B
#define SMEM_MMA (2 * STAGE_B)        // 73728 (tile 128*129*4=66048 fits in reuse)
#define NC (Dh / 64)                  // 16 k-chunks of 64
#define TSTRIDE 129                   // tile row stride in floats

__global__ __launch_bounds__(256, 2)
void sim_mma_kernel() {
    extern __shared__ __align__(128) char smem[];
    uint32_t sb = smem_u32(smem);
    int tid = threadIdx.x;
    int lane = tid & 31;
    int wid = tid >> 5;
    int warp_m = wid >> 2;
    int warp_n = wid & 3;

    // decode lower-triangular tile (bi >= bj)
    int tix = blockIdx.x;
    int bi = (int)((sqrtf(8.0f * (float)tix + 1.0f) - 1.0f) * 0.5f);
    while ((bi + 1) * (bi + 2) / 2 <= tix) bi++;
    while (bi * (bi + 1) / 2 > tix) bi--;
    int bj = tix - bi * (bi + 1) / 2;
    int rbase = bi * 128;
    int cbase = bj * 128;

    float acc[4][4][4];
#pragma unroll
    for (int mt = 0; mt < 4; mt++)
#pragma unroll
        for (int nt = 0; nt < 4; nt++)
#pragma unroll
            for (int q = 0; q < 4; q++) acc[mt][nt][q] = 0.0f;

    // 2048 x 16B lines per chunk, 8 per thread
    auto issue = [&](int kc, int buf) {
#pragma unroll
        for (int i = 0; i < 8; i++) {
            int plane = i >> 2;                    // 0:A 1:B
            int idx = tid + (i & 3) * 256;         // 0..1023
            int row = idx >> 3;                    // 0..127
            int q = idx & 7;                       // 16B chunk in 128B row
            int grow = ((plane == 0) ? rbase : cbase) + row;
            const __half* src = g_hf + (size_t)grow * Dh + kc * 64 + q * 8;
            uint32_t dst = sb + buf * STAGE_B + plane * PLANE_B + row * ROWB + q * 16;
            cp16(dst, src);
        }
        CP_COMMIT();
    };

    uint32_t a_off = (uint32_t)((warp_m * 64 + (lane & 15)) * ROWB + ((lane >> 4) & 1) * 16);
    int bmat = lane >> 3, brin = lane & 7;
    uint32_t b_row0 = (uint32_t)(warp_n * 32 + ((bmat >> 1) & 1) * 8 + brin);
    uint32_t b_off = b_row0 * ROWB + (uint32_t)((bmat & 1) * 16);

    issue(0, 0);
    for (int kc = 0; kc < NC; kc++) {
        int buf = kc & 1;
        CP_WAIT0();              // chunk for buf (issued last iter) has landed
        __syncthreads();         // and everyone finished reading buf^1
        if (kc + 1 < NC) issue(kc + 1, buf ^ 1);

        uint32_t st = sb + buf * STAGE_B;
#pragma unroll
        for (int ks = 0; ks < 4; ks++) {
            uint32_t ah[4][4], bh[4][2];
#pragma unroll
            for (int mt = 0; mt < 4; mt++) {
                uint32_t addr = st + a_off + (uint32_t)(mt * 16 * ROWB + ks * 32);
                LDSM4(ah[mt][0], ah[mt][1], ah[mt][2], ah[mt][3], addr);
            }
#pragma unroll
            for (int p = 0; p < 2; p++) {
                uint32_t addr = st + PLANE_B + b_off + (uint32_t)(p * 16 * ROWB + ks * 32);
                uint32_t r0, r1, r2, r3;
                LDSM4(r0, r1, r2, r3, addr);
                bh[p * 2][0] = r0; bh[p * 2][1] = r1; bh[p * 2 + 1][0] = r2; bh[p * 2 + 1][1] = r3;
            }
#pragma unroll
            for (int mt = 0; mt < 4; mt++)
#pragma unroll
                for (int nt = 0; nt < 4; nt++) mma_fp16(acc[mt][nt], ah[mt], bh[nt]);
        }
    }
    __syncthreads();   // last compute done before smem reuse as tile

    // ---- stage scaled tile (x2 = /temperature) into smem [128][129] ----
    float* tile = (float*)smem;
#pragma unroll
    for (int mt = 0; mt < 4; mt++) {
#pragma unroll
        for (int h = 0; h < 2; h++) {
            int rloc = warp_m * 64 + mt * 16 + h * 8 + (lane >> 2);
#pragma unroll
            for (int nt = 0; nt < 4; nt++) {
                int c = warp_n * 32 + nt * 8 + (lane & 3) * 2;
                tile[rloc * TSTRIDE + c]     = acc[mt][nt][h * 2 + 0] * 2.0f;
                tile[rloc * TSTRIDE + c + 1] = acc[mt][nt][h * 2 + 1] * 2.0f;
            }
        }
    }
    __syncthreads();

    // ---- dual-sided masked LSE over the tile ----
    if (tid < 128) {
        int rmod = (rbase + tid) & (Bsz - 1);
        int cw0 = ((cbase & (Bsz - 1)) >> 5);
        uint32_t w[4];
#pragma unroll
        for (int q = 0; q < 4; q++) w[q] = g_adj[rmod * (Bsz / 32) + cw0 + q];
        const float* rowp = tile + tid * TSTRIDE;
        float M = -FLT_MAX;
#pragma unroll 4
        for (int c = 0; c < 128; c++) {
            if (!((w[c >> 5] >> (c & 31)) & 1u)) M = fmaxf(M, rowp[c]);
        }
        float S = 0.0f;
        if (M > -FLT_MAX * 0.5f) {
#pragma unroll 4
            for (int c = 0; c < 128; c++) {
                if (!((w[c >> 5] >> (c & 31)) & 1u)) S += __expf(rowp[c] - M);
            }
        }
        g_part[(size_t)(rbase + tid) * CBLK + bj] = make_float2(M, S);
    } else if (bi != bj) {
        int u = tid - 128;
        int rmod = (cbase + u) & (Bsz - 1);
        int cw0 = ((rbase & (Bsz - 1)) >> 5);
        uint32_t w[4];
#pragma unroll
        for (int q = 0; q < 4; q++) w[q] = g_adj[rmod * (Bsz / 32) + cw0 + q];
        const float* colp = tile + u;
        float M = -FLT_MAX;
#pragma unroll 4
        for (int r = 0; r < 128; r++) {
            if (!((w[r >> 5] >> (r & 31)) & 1u)) M = fmaxf(M, colp[r * TSTRIDE]);
        }
        float S = 0.0f;
        if (M > -FLT_MAX * 0.5f) {
#pragma unroll 4
            for (int r = 0; r < 128; r++) {
                if (!((w[r >> 5] >> (r & 31)) & 1u)) S += __expf(colp[r * TSTRIDE] - M);
            }
        }
        g_part[(size_t)(cbase + u) * CBLK + bi] = make_float2(M, S);
    }
}

// ---------------- finalize stage 1: one warp per row ----------------
__global__ void rowlse_kernel() {
    int warp = (blockIdx.x * blockDim.x + threadIdx.x) >> 5;   // 0..8191
    int lane = threadIdx.x & 31;
    const float2* p = &g_part[(size_t)warp * CBLK];
    float M = -FLT_MAX, S = 0.0f;
    float2 q0 = p[lane];
    float2 q1 = p[lane + 32];
    lse_merge(M, S, q0.x, q0.y);
    lse_merge(M, S, q1.x, q1.y);
#pragma unroll
    for (int o = 16; o; o >>= 1) {
        float m2 = __shfl_xor_sync(0xffffffffu, M, o);
        float s2 = __shfl_xor_sync(0xffffffffu, S, o);
        lse_merge(M, S, m2, s2);
    }
    if (lane == 0) {
        float pos = g_pos[warp & (Bsz - 1)];
        lse_merge(M, S, pos, 1.0f);
        g_row[warp] = (M + __logf(S)) - pos;
    }
}

// ---------------- finalize stage 2 ----------------
__global__ void final_reduce(float* __restrict__ out) {
    __shared__ double sred[256];
    int t = threadIdx.x;
    double acc = 0.0;
    for (int r = t; r < RTOT; r += 256) acc += (double)g_row[r];
    sred[t] = acc;
    __syncthreads();
    for (int o = 128; o; o >>= 1) {
        if (t < o) sred[t] += sred[t + o];
        __syncthreads();
    }
    if (t == 0) out[0] = (float)(sred[0] / (double)RTOT);
}

// ---------------- launch ----------------
extern "C" void kernel_launch(void* const* d_in, const int* in_sizes, int n_in,
                              void* d_out, int out_size) {
    const float* hi    = (const float*)d_in[0];
    const float* hj    = (const float*)d_in[1];
    const float* P     = (const float*)d_in[2];
    const float* noise = (const float*)d_in[3];
    (void)in_sizes; (void)n_in; (void)out_size;

    static int smem_set = 0;
    if (!smem_set) {
        cudaFuncSetAttribute(sim_mma_kernel, cudaFuncAttributeMaxDynamicSharedMemorySize, SMEM_MMA);
        smem_set = 1;
    }

    maskP_kernel<<<(Bsz * 32 + 255) / 256, 256>>>(P);
    adj_kernel<<<Bsz, 256>>>(noise);
    splitpos_kernel<<<Bsz * 32 / 256, 256>>>(hi, hj);
    sim_mma_kernel<<<NTILE, 256, SMEM_MMA>>>();
    rowlse_kernel<<<RTOT * 32 / 256, 256>>>();
    final_reduce<<<1, 256>>>((float*)d_out);
}

// round 17
// speedup vs baseline: 1.0729x; 1.0041x over previous
#include <cuda_runtime.h>
#include <cuda_fp16.h>
#include <math.h>
#include <float.h>
#include <stdint.h>

#define Bsz   4096
#define Dh    1024
#define Cdim  128
#define KSEL  10
#define RTOT  8192
#define CBLK  64
#define NTILE 2080          // 64*65/2 lower-triangular tiles

// ---------------- scratch ----------------
__device__ float     g_v[Bsz];
__device__ float     g_sq[Bsz];                // cc * vc^2
__device__ float2    g_vsq[Bsz];               // (v, cc*v^2) packed
__device__ signed char g_amax[Bsz];            // argmax if unique, else -1
__device__ uint32_t  g_mask[Bsz][4];
__device__ uint32_t  g_adj[Bsz * (Bsz / 32)];
__device__ float2    g_part[(size_t)RTOT * CBLK];
__device__ float     g_pos[Bsz];
__device__ float     g_row[RTOT];
__device__ __align__(256) __half g_hf[(size_t)RTOT * Dh];   // 16MB fp16 plane

// ================= helpers =================
__device__ __forceinline__ uint32_t smem_u32(const void* p) {
    uint32_t a;
    asm("{ .reg .u64 t; cvta.to.shared.u64 t, %1; cvt.u32.u64 %0, t; }" : "=r"(a) : "l"(p));
    return a;
}
__device__ __forceinline__ void cp16(uint32_t d, const void* s) {
    asm volatile("cp.async.ca.shared.global [%0], [%1], 16;" :: "r"(d), "l"(s) : "memory");
}
#define CP_COMMIT() asm volatile("cp.async.commit_group;" ::: "memory")
#define CP_WAIT0()  asm volatile("cp.async.wait_group 0;" ::: "memory")
#define LDSM4(r0, r1, r2, r3, a) \
    asm volatile("ldmatrix.sync.aligned.m8n8.x4.shared.b16 {%0,%1,%2,%3}, [%4];" \
        : "=r"(r0), "=r"(r1), "=r"(r2), "=r"(r3) : "r"(a))

__device__ __forceinline__ void mma_fp16(float* d, const uint32_t* a, const uint32_t* b) {
    asm volatile(
        "mma.sync.aligned.m16n8k16.row.col.f32.f16.f16.f32 "
        "{%0,%1,%2,%3}, {%4,%5,%6,%7}, {%8,%9}, {%0,%1,%2,%3};"
        : "+f"(d[0]), "+f"(d[1]), "+f"(d[2]), "+f"(d[3])
        : "r"(a[0]), "r"(a[1]), "r"(a[2]), "r"(a[3]), "r"(b[0]), "r"(b[1]));
}
__device__ __forceinline__ void lse_merge(float& M, float& S, float m2, float s2) {
    if (m2 > M) { S = s2 + S * __expf(M - m2); M = m2; }
    else if (s2 > 0.0f) { S += s2 * __expf(m2 - M); }
}

// ---------------- fused prep: maskP (blocks 0-511) + splitpos (blocks 512-1023) ----------------
__global__ void prep_kernel(const float* __restrict__ P,
                            const float* __restrict__ hi, const float* __restrict__ hj) {
    int lane = threadIdx.x & 31;
    if (blockIdx.x < 512) {
        // ---- maskP: one warp per P row ----
        int warp = (blockIdx.x * blockDim.x + threadIdx.x) >> 5;
        if (warp >= Bsz) return;
        const float* row = P + (size_t)warp * Cdim;
        float v[4];
        float m = -FLT_MAX;
#pragma unroll
        for (int j = 0; j < 4; j++) { v[j] = row[j * 32 + lane]; m = fmaxf(m, v[j]); }
#pragma unroll
        for (int o = 16; o; o >>= 1) m = fmaxf(m, __shfl_xor_sync(0xffffffffu, m, o));
        uint32_t bb[4];
        int cnt = 0;
#pragma unroll
        for (int j = 0; j < 4; j++) {
            bb[j] = __ballot_sync(0xffffffffu, v[j] == m);
            cnt += __popc(bb[j]);
            if (lane == 0) g_mask[warp][j] = bb[j];
        }
        if (lane == 0) {
            int amax = -1;
#pragma unroll
            for (int j = 3; j >= 0; j--) {
                if (bb[j]) amax = j * 32 + __ffs(bb[j]) - 1;
            }
            g_v[warp] = m;
            g_sq[warp] = (float)cnt * m * m;
            g_vsq[warp] = make_float2(m, (float)cnt * m * m);
            g_amax[warp] = (cnt == 1) ? (signed char)amax : (signed char)(-1);
        }
    } else {
        // ---- splitpos: one warp per (hi,hj) row pair ----
        int warp = ((blockIdx.x - 512) * blockDim.x + threadIdx.x) >> 5;
        if (warp >= Bsz) return;
        const float4* a = (const float4*)(hi + (size_t)warp * Dh);
        const float4* b = (const float4*)(hj + (size_t)warp * Dh);
        __half2* da = (__half2*)(g_hf + (size_t)warp * Dh);
        __half2* db = (__half2*)(g_hf + (size_t)(warp + Bsz) * Dh);
        float s = 0.0f;
        for (int i = lane; i < Dh / 4; i += 32) {
            float4 x = a[i], y = b[i];
            s += x.x * y.x + x.y * y.y + x.z * y.z + x.w * y.w;
            da[i * 2]     = __floats2half2_rn(x.x, x.y);
            da[i * 2 + 1] = __floats2half2_rn(x.z, x.w);
            db[i * 2]     = __floats2half2_rn(y.x, y.y);
            db[i * 2 + 1] = __floats2half2_rn(y.z, y.w);
        }
#pragma unroll
        for (int o = 16; o; o >>= 1) s += __shfl_xor_sync(0xffffffffu, s, o);
        if (lane == 0) g_pos[warp] = s * 2.0f;   // /temperature(0.5)
    }
}

// ---------------- Kernel B: adjacency via d^2 top-k (argmax fast path) ----------------
__global__ __launch_bounds__(256) void adj_kernel(const float* __restrict__ noise) {
    __shared__ float wval[128];
    __shared__ int   widx[128];
    __shared__ int   winlist[16];
    int r = blockIdx.x;
    int t = threadIdx.x;      // 256
    int lane = t & 31, w = t >> 5;

    float vr = g_v[r];
    float sqr = g_sq[r];
    int ar = g_amax[r];

    // phase 1: thread-local top-8 smallest d^2 over 16 columns
    float tv[8]; int ti[8];
#pragma unroll
    for (int i = 0; i < 8; i++) { tv[i] = FLT_MAX; ti[i] = -1; }

    if (ar >= 0) {
        float two_vr = 2.0f * vr;
#pragma unroll
        for (int i = 0; i < 16; i++) {
            int c = i * 256 + t;
            int ac = g_amax[c];
            float2 vs = g_vsq[c];
            float d2;
            if (ac >= 0) {
                d2 = sqr + vs.y - ((ac == ar) ? two_vr * vs.x : 0.0f);
            } else {
                int nc = (g_mask[c][ar >> 5] >> (ar & 31)) & 1;
                d2 = sqr + vs.y - two_vr * vs.x * (float)nc;
            }
            if (d2 < tv[7]) {
                tv[7] = d2; ti[7] = c;
#pragma unroll
                for (int j = 7; j > 0; j--) {
                    if (tv[j] < tv[j - 1]) {
                        float tf = tv[j - 1]; tv[j - 1] = tv[j]; tv[j] = tf;
                        int tx = ti[j - 1]; ti[j - 1] = ti[j]; ti[j] = tx;
                    } else break;
                }
            }
        }
    } else {
        uint32_t mr0 = g_mask[r][0], mr1 = g_mask[r][1], mr2 = g_mask[r][2], mr3 = g_mask[r][3];
#pragma unroll
        for (int i = 0; i < 16; i++) {
            int c = i * 256 + t;
            int nc = __popc(mr0 & g_mask[c][0]) + __popc(mr1 & g_mask[c][1]) +
                     __popc(mr2 & g_mask[c][2]) + __popc(mr3 & g_mask[c][3]);
            float2 vs = g_vsq[c];
            float d2 = sqr + vs.y - 2.0f * vr * vs.x * (float)nc;
            if (d2 < tv[7]) {
                tv[7] = d2; ti[7] = c;
#pragma unroll
                for (int j = 7; j > 0; j--) {
                    if (tv[j] < tv[j - 1]) {
                        float tf = tv[j - 1]; tv[j - 1] = tv[j]; tv[j] = tf;
                        int tx = ti[j - 1]; ti[j - 1] = ti[j]; ti[j] = tx;
                    } else break;
                }
            }
        }
    }

    // phase 2: per-warp top-16 (argmin with list advance)
#pragma unroll
    for (int it = 0; it < 16; it++) {
        float bv = tv[0]; int bl = lane;
#pragma unroll
        for (int o = 16; o; o >>= 1) {
            float ov = __shfl_xor_sync(0xffffffffu, bv, o);
            int   ol = __shfl_xor_sync(0xffffffffu, bl, o);
            if (ov < bv || (ov == bv && ol < bl)) { bv = ov; bl = ol; }
        }
        int bidx = __shfl_sync(0xffffffffu, ti[0], bl);
        if (lane == 0) { wval[w * 16 + it] = bv; widx[w * 16 + it] = bidx; }
        if (lane == bl) {
#pragma unroll
            for (int j = 0; j < 7; j++) { tv[j] = tv[j + 1]; ti[j] = ti[j + 1]; }
            tv[7] = FLT_MAX;
        }
    }
    __syncthreads();

    // phase 3 (warp 0): top-20 of 128 by d^2, exact S on those, top-10 by S
    if (w == 0) {
        float cvv[4]; int cii[4];
#pragma unroll
        for (int j = 0; j < 4; j++) { cvv[j] = wval[j * 32 + lane]; cii[j] = widx[j * 32 + lane]; }
        float myd2 = FLT_MAX; int myidx = -1;
#pragma unroll
        for (int it = 0; it < 20; it++) {
            float bv = cvv[0]; int bi = cii[0];
            if (cvv[1] < bv) { bv = cvv[1]; bi = cii[1]; }
            if (cvv[2] < bv) { bv = cvv[2]; bi = cii[2]; }
            if (cvv[3] < bv) { bv = cvv[3]; bi = cii[3]; }
            int bl = lane;
            float rv = bv; int rl = bl;
#pragma unroll
            for (int o = 16; o; o >>= 1) {
                float ov = __shfl_xor_sync(0xffffffffu, rv, o);
                int   ol = __shfl_xor_sync(0xffffffffu, rl, o);
                if (ov < rv || (ov == rv && ol < rl)) { rv = ov; rl = ol; }
            }
            int bidx = __shfl_sync(0xffffffffu, bi, rl);
            if (lane == it) { myd2 = rv; myidx = bidx; }
            if (lane == rl) {
                if      (cvv[0] == rv && cii[0] == bidx) cvv[0] = FLT_MAX;
                else if (cvv[1] == rv && cii[1] == bidx) cvv[1] = FLT_MAX;
                else if (cvv[2] == rv && cii[2] == bidx) cvv[2] = FLT_MAX;
                else                                     cvv[3] = FLT_MAX;
            }
        }
        float s;
        if (lane < 20 && myidx >= 0) {
            float d2c = fmaxf(myd2, 0.0f);
            float nz = noise[(size_t)r * Bsz + myidx];
            s = -(sqrtf(d2c) + 1e-4f * nz - (myidx == r ? 1.0f : 0.0f));
        } else s = -FLT_MAX;
#pragma unroll
        for (int it = 0; it < 10; it++) {
            float rv = s; int rl = lane;
#pragma unroll
            for (int o = 16; o; o >>= 1) {
                float ov = __shfl_xor_sync(0xffffffffu, rv, o);
                int   ol = __shfl_xor_sync(0xffffffffu, rl, o);
                if (ov > rv || (ov == rv && ol < rl)) { rv = ov; rl = ol; }
            }
            int bidx = __shfl_sync(0xffffffffu, myidx, rl);
            if (lane == 0) winlist[it] = bidx;
            if (lane == rl) s = -FLT_MAX;
        }
    }
    __syncthreads();

    // phase 4: emit bitmask row (10 set bits)
    if (t < 128) {
        uint32_t word = 0;
#pragma unroll
        for (int j = 0; j < 10; j++) {
            int ix = winlist[j];
            if ((ix >> 5) == t) word |= 1u << (ix & 31);
        }
        g_adj[r * 128 + t] = word;
    }
}

// ---------------- sim GEMM: fp16, KC=64 chunks, triangular tiles (R15-proven mainloop) ----------------
#define ROWB 144                      // 128B data + 16B pad (conflict-free ldmatrix)
#define PLANE_B (128 * ROWB)          // 18432
#define STAGE_B (2 * PLANE_B)         // 36864: A, B
#define SMEM_MMA (2 * STAGE_B)        // 73728 (tile 128*129*4=66048 fits in reuse)
#define NC (Dh / 64)                  // 16 k-chunks of 64
#define TSTRIDE 129                   // tile row stride in floats

__global__ __launch_bounds__(256, 2)
void sim_mma_kernel() {
    extern __shared__ __align__(128) char smem[];
    uint32_t sb = smem_u32(smem);
    int tid = threadIdx.x;
    int lane = tid & 31;
    int wid = tid >> 5;
    int warp_m = wid >> 2;
    int warp_n = wid & 3;

    // decode lower-triangular tile (bi >= bj)
    int tix = blockIdx.x;
    int bi = (int)((sqrtf(8.0f * (float)tix + 1.0f) - 1.0f) * 0.5f);
    while ((bi + 1) * (bi + 2) / 2 <= tix) bi++;
    while (bi * (bi + 1) / 2 > tix) bi--;
    int bj = tix - bi * (bi + 1) / 2;
    int rbase = bi * 128;
    int cbase = bj * 128;

    float acc[4][4][4];
#pragma unroll
    for (int mt = 0; mt < 4; mt++)
#pragma unroll
        for (int nt = 0; nt < 4; nt++)
#pragma unroll
            for (int q = 0; q < 4; q++) acc[mt][nt][q] = 0.0f;

    // 2048 x 16B lines per chunk, 8 per thread
    auto issue = [&](int kc, int buf) {
#pragma unroll
        for (int i = 0; i < 8; i++) {
            int plane = i >> 2;                    // 0:A 1:B
            int idx = tid + (i & 3) * 256;         // 0..1023
            int row = idx >> 3;                    // 0..127
            int q = idx & 7;                       // 16B chunk in 128B row
            int grow = ((plane == 0) ? rbase : cbase) + row;
            const __half* src = g_hf + (size_t)grow * Dh + kc * 64 + q * 8;
            uint32_t dst = sb + buf * STAGE_B + plane * PLANE_B + row * ROWB + q * 16;
            cp16(dst, src);
        }
        CP_COMMIT();
    };

    uint32_t a_off = (uint32_t)((warp_m * 64 + (lane & 15)) * ROWB + ((lane >> 4) & 1) * 16);
    int bmat = lane >> 3, brin = lane & 7;
    uint32_t b_row0 = (uint32_t)(warp_n * 32 + ((bmat >> 1) & 1) * 8 + brin);
    uint32_t b_off = b_row0 * ROWB + (uint32_t)((bmat & 1) * 16);

    issue(0, 0);
    for (int kc = 0; kc < NC; kc++) {
        int buf = kc & 1;
        CP_WAIT0();              // chunk for buf (issued last iter) has landed
        __syncthreads();         // publish ALL threads' copies + buf^1 readers done
        if (kc + 1 < NC) issue(kc + 1, buf ^ 1);

        uint32_t st = sb + buf * STAGE_B;
#pragma unroll
        for (int ks = 0; ks < 4; ks++) {
            uint32_t ah[4][4], bh[4][2];
#pragma unroll
            for (int mt = 0; mt < 4; mt++) {
                uint32_t addr = st + a_off + (uint32_t)(mt * 16 * ROWB + ks * 32);
                LDSM4(ah[mt][0], ah[mt][1], ah[mt][2], ah[mt][3], addr);
            }
#pragma unroll
            for (int p = 0; p < 2; p++) {
                uint32_t addr = st + PLANE_B + b_off + (uint32_t)(p * 16 * ROWB + ks * 32);
                uint32_t r0, r1, r2, r3;
                LDSM4(r0, r1, r2, r3, addr);
                bh[p * 2][0] = r0; bh[p * 2][1] = r1; bh[p * 2 + 1][0] = r2; bh[p * 2 + 1][1] = r3;
            }
#pragma unroll
            for (int mt = 0; mt < 4; mt++)
#pragma unroll
                for (int nt = 0; nt < 4; nt++) mma_fp16(acc[mt][nt], ah[mt], bh[nt]);
        }
    }
    __syncthreads();   // last compute done before smem reuse as tile

    // ---- stage scaled tile (x2 = /temperature) into smem [128][129] ----
    float* tile = (float*)smem;
#pragma unroll
    for (int mt = 0; mt < 4; mt++) {
#pragma unroll
        for (int h = 0; h < 2; h++) {
            int rloc = warp_m * 64 + mt * 16 + h * 8 + (lane >> 2);
#pragma unroll
            for (int nt = 0; nt < 4; nt++) {
                int c = warp_n * 32 + nt * 8 + (lane & 3) * 2;
                tile[rloc * TSTRIDE + c]     = acc[mt][nt][h * 2 + 0] * 2.0f;
                tile[rloc * TSTRIDE + c + 1] = acc[mt][nt][h * 2 + 1] * 2.0f;
            }
        }
    }
    __syncthreads();

    // ---- dual-sided masked LSE over the tile ----
    if (tid < 128) {
        int rmod = (rbase + tid) & (Bsz - 1);
        int cw0 = ((cbase & (Bsz - 1)) >> 5);
        uint32_t w[4];
#pragma unroll
        for (int q = 0; q < 4; q++) w[q] = g_adj[rmod * (Bsz / 32) + cw0 + q];
        const float* rowp = tile + tid * TSTRIDE;
        float M = -FLT_MAX;
#pragma unroll 4
        for (int c = 0; c < 128; c++) {
            if (!((w[c >> 5] >> (c & 31)) & 1u)) M = fmaxf(M, rowp[c]);
        }
        float S = 0.0f;
        if (M > -FLT_MAX * 0.5f) {
#pragma unroll 4
            for (int c = 0; c < 128; c++) {
                if (!((w[c >> 5] >> (c & 31)) & 1u)) S += __expf(rowp[c] - M);
            }
        }
        g_part[(size_t)(rbase + tid) * CBLK + bj] = make_float2(M, S);
    } else if (bi != bj) {
        int u = tid - 128;
        int rmod = (cbase + u) & (Bsz - 1);
        int cw0 = ((rbase & (Bsz - 1)) >> 5);
        uint32_t w[4];
#pragma unroll
        for (int q = 0; q < 4; q++) w[q] = g_adj[rmod * (Bsz / 32) + cw0 + q];
        const float* colp = tile + u;
        float M = -FLT_MAX;
#pragma unroll 4
        for (int r = 0; r < 128; r++) {
            if (!((w[r >> 5] >> (r & 31)) & 1u)) M = fmaxf(M, colp[r * TSTRIDE]);
        }
        float S = 0.0f;
        if (M > -FLT_MAX * 0.5f) {
#pragma unroll 4
            for (int r = 0; r < 128; r++) {
                if (!((w[r >> 5] >> (r & 31)) & 1u)) S += __expf(colp[r * TSTRIDE] - M);
            }
        }
        g_part[(size_t)(cbase + u) * CBLK + bi] = make_float2(M, S);
    }
}

// ---------------- finalize stage 1: one warp per row ----------------
__global__ void rowlse_kernel() {
    int warp = (blockIdx.x * blockDim.x + threadIdx.x) >> 5;   // 0..8191
    int lane = threadIdx.x & 31;
    const float2* p = &g_part[(size_t)warp * CBLK];
    float M = -FLT_MAX, S = 0.0f;
    float2 q0 = p[lane];
    float2 q1 = p[lane + 32];
    lse_merge(M, S, q0.x, q0.y);
    lse_merge(M, S, q1.x, q1.y);
#pragma unroll
    for (int o = 16; o; o >>= 1) {
        float m2 = __shfl_xor_sync(0xffffffffu, M, o);
        float s2 = __shfl_xor_sync(0xffffffffu, S, o);
        lse_merge(M, S, m2, s2);
    }
    if (lane == 0) {
        float pos = g_pos[warp & (Bsz - 1)];
        lse_merge(M, S, pos, 1.0f);
        g_row[warp] = (M + __logf(S)) - pos;
    }
}

// ---------------- finalize stage 2 ----------------
__global__ void final_reduce(float* __restrict__ out) {
    __shared__ double sred[256];
    int t = threadIdx.x;
    double acc = 0.0;
    for (int r = t; r < RTOT; r += 256) acc += (double)g_row[r];
    sred[t] = acc;
    __syncthreads();
    for (int o = 128; o; o >>= 1) {
        if (t < o) sred[t] += sred[t + o];
        __syncthreads();
    }
    if (t == 0) out[0] = (float)(sred[0] / (double)RTOT);
}

// ---------------- launch ----------------
extern "C" void kernel_launch(void* const* d_in, const int* in_sizes, int n_in,
                              void* d_out, int out_size) {
    const float* hi    = (const float*)d_in[0];
    const float* hj    = (const float*)d_in[1];
    const float* P     = (const float*)d_in[2];
    const float* noise = (const float*)d_in[3];
    (void)in_sizes; (void)n_in; (void)out_size;

    static int smem_set = 0;
    if (!smem_set) {
        cudaFuncSetAttribute(sim_mma_kernel, cudaFuncAttributeMaxDynamicSharedMemorySize, SMEM_MMA);
        smem_set = 1;
    }

    prep_kernel<<<1024, 256>>>(P, hi, hj);
    adj_kernel<<<Bsz, 256>>>(noise);
    sim_mma_kernel<<<NTILE, 256, SMEM_MMA>>>();
    rowlse_kernel<<<RTOT * 32 / 256, 256>>>();
    final_reduce<<<1, 256>>>((float*)d_out);
}